// round 12
// baseline (speedup 1.0000x reference)
#include <cuda_runtime.h>
#include <cstdint>
#include <climits>

#define N_BINS 85
#define NBLOCKS 592                    // 4 CTAs/SM * 148 SMs (smem-limited)
#define BLOCK_THREADS 256
#define ACTIVE_THREADS 255
#define M_SUPER 6                      // super-rows per chunk
#define CHUNK_F4 (M_SUPER * N_BINS)    // 510 float4 per array per chunk
#define CHUNK_BYTES (CHUNK_F4 * 16)    // 8160
#define CHUNK_FLOATS (CHUNK_F4 * 4)    // 2040
#define STAGE_BYTES (2 * CHUNK_BYTES)  // 16320: [in | tg]
#define NSTAGES 3
#define DYN_SMEM (NSTAGES * STAGE_BYTES)   // 48960

// Globals (zero at module load; last block resets via atomicExch each call,
// so graph replays are deterministic). No dynamic allocation.
__device__ float g_acc[N_BINS];
__device__ unsigned int g_count;
__device__ unsigned int g_work;

__device__ __forceinline__ uint32_t smem_u32(const void* p) {
    return (uint32_t)__cvta_generic_to_shared(p);
}
__device__ __forceinline__ void mbar_init(uint32_t a, uint32_t cnt) {
    asm volatile("mbarrier.init.shared.b64 [%0], %1;" :: "r"(a), "r"(cnt) : "memory");
}
__device__ __forceinline__ void mbar_expect_tx(uint32_t a, uint32_t bytes) {
    asm volatile("mbarrier.arrive.expect_tx.shared.b64 _, [%0], %1;"
                 :: "r"(a), "r"(bytes) : "memory");
}
__device__ __forceinline__ void mbar_arrive(uint32_t a) {
    asm volatile("mbarrier.arrive.shared.b64 _, [%0];" :: "r"(a) : "memory");
}
__device__ __forceinline__ void bulk_g2s(uint32_t dst, const void* src,
                                         uint32_t bytes, uint32_t mbar) {
    asm volatile(
        "cp.async.bulk.shared::cluster.global.mbarrier::complete_tx::bytes "
        "[%0], [%1], %2, [%3];"
        :: "r"(dst), "l"(src), "r"(bytes), "r"(mbar) : "memory");
}
__device__ __forceinline__ void mbar_wait(uint32_t a, uint32_t parity) {
    uint32_t done;
    asm volatile(
        "{\n\t.reg .pred p;\n\t"
        "mbarrier.try_wait.parity.acquire.cta.shared::cta.b64 p, [%1], %2;\n\t"
        "selp.b32 %0, 1, 0, p;\n\t}"
        : "=r"(done) : "r"(a), "r"(parity) : "memory");
    if (!done) {
        asm volatile(
            "{\n\t.reg .pred P1;\n\t"
            "W%=:\n\t"
            "mbarrier.try_wait.parity.acquire.cta.shared::cta.b64 P1, [%0], %1, 0x989680;\n\t"
            "@P1 bra.uni D%=;\n\t"
            "bra.uni W%=;\n\t"
            "D%=:\n\t}"
            :: "r"(a), "r"(parity) : "memory");
    }
}

extern __shared__ __align__(128) char dynbuf[];   // NSTAGES * STAGE_BYTES

// ---------------------------------------------------------------------------
// Dynamically-scheduled TMA pipeline:
//  * t0 pops chunk ids from a global atomic queue and streams them into SMEM
//    via cp.async.bulk (3 stages, mbarrier expect_tx). One ATOMG per 16 KB,
//    issued off the critical path -> no straggler tail from static partition.
//  * consumers never need the chunk id: the fixed-column accumulator map
//    (col of float4-slot j = (4j+k)%85) is chunk-invariant.
//  * queue exhaustion: t0 sets s_stop and flips the slot barrier with a
//    plain (no-tx) arrive; consumers break at w == s_stop.
// Epilogue: one fence/block + ticket; last block finishes (proven cheap).
// ---------------------------------------------------------------------------
__global__ void __launch_bounds__(BLOCK_THREADS, 4)
emd_fused(const float* __restrict__ in, const float* __restrict__ tg,
          int nchunk, int tail_start, int total_elems, float* __restrict__ out)
{
    __shared__ __align__(8) unsigned long long mbar[NSTAGES];
    __shared__ float sd[N_BINS];
    __shared__ int islast;
    __shared__ volatile int s_stop;
    int t = threadIdx.x;
    if (t < N_BINS) sd[t] = 0.0f;
    if (t == 0) {
        s_stop = INT_MAX;
        #pragma unroll
        for (int s = 0; s < NSTAGES; s++) mbar_init(smem_u32(&mbar[s]), 1);
    }
    __syncthreads();
    asm volatile("fence.proxy.async.shared::cta;" ::: "memory");

    // Prologue: t0 pops up to NSTAGES chunks and fills the pipeline.
    if (t == 0) {
        for (int w = 0; w < NSTAGES; w++) {
            uint32_t mb  = smem_u32(&mbar[w]);
            int c = (int)atomicAdd(&g_work, 1u);
            if (c < nchunk) {
                uint32_t dst = smem_u32(dynbuf + w * STAGE_BYTES);
                mbar_expect_tx(mb, STAGE_BYTES);
                bulk_g2s(dst,               in + (size_t)c * CHUNK_FLOATS, CHUNK_BYTES, mb);
                bulk_g2s(dst + CHUNK_BYTES, tg + (size_t)c * CHUNK_FLOATS, CHUNK_BYTES, mb);
            } else {
                if (w < s_stop) s_stop = w;
                mbar_arrive(mb);           // flip with no data
            }
        }
    }

    float a0 = 0.f, a1 = 0.f, a2 = 0.f, a3 = 0.f;
    int g = t / N_BINS;                    // 0..2 active; 3 for t=255 (idle)
    int p = t % N_BINS;
    int j1 = p + N_BINS * g;               // float4 slots this thread owns
    int j2 = j1 + ACTIVE_THREADS;          // +255

    for (int w = 0; ; w++) {
        int slot = w % NSTAGES;
        uint32_t parity = (uint32_t)(w / NSTAGES) & 1u;
        mbar_wait(smem_u32(&mbar[slot]), parity);
        if (w >= s_stop) break;            // acquire-wait ordered t0's write

        if (t < ACTIVE_THREADS) {
            const float4* sin = (const float4*)(dynbuf + slot * STAGE_BYTES);
            const float4* stg = (const float4*)(dynbuf + slot * STAGE_BYTES + CHUNK_BYTES);
            float4 xa = sin[j1], ya = sin[j2];
            float4 xb = stg[j1], yb = stg[j2];
            a0 += (xa.x - xb.x) + (ya.x - yb.x);
            a1 += (xa.y - xb.y) + (ya.y - yb.y);
            a2 += (xa.z - xb.z) + (ya.z - yb.z);
            a3 += (xa.w - xb.w) + (ya.w - yb.w);
        }
        __syncthreads();                   // slot fully consumed by all threads
        if (t == 0) {
            int wn = w + NSTAGES;
            uint32_t mb  = smem_u32(&mbar[slot]);
            int c = (int)atomicAdd(&g_work, 1u);
            if (c < nchunk) {
                uint32_t dst = smem_u32(dynbuf + slot * STAGE_BYTES);
                mbar_expect_tx(mb, STAGE_BYTES);
                bulk_g2s(dst,               in + (size_t)c * CHUNK_FLOATS, CHUNK_BYTES, mb);
                bulk_g2s(dst + CHUNK_BYTES, tg + (size_t)c * CHUNK_FLOATS, CHUNK_BYTES, mb);
            } else {
                if (wn < s_stop) s_stop = wn;
                mbar_arrive(mb);
            }
        }
    }

    // Fold register lanes into fixed columns (4p+k) mod 85.
    if (t < ACTIVE_THREADS) {
        atomicAdd(&sd[(4 * p) % N_BINS],     a0);
        atomicAdd(&sd[(4 * p + 1) % N_BINS], a1);
        atomicAdd(&sd[(4 * p + 2) % N_BINS], a2);
        atomicAdd(&sd[(4 * p + 3) % N_BINS], a3);
    }
    // Tail elements not covered by chunks: block 0, scalar LDG.
    if (blockIdx.x == 0) {
        for (int i = tail_start + t; i < total_elems; i += BLOCK_THREADS) {
            atomicAdd(&sd[i % N_BINS], in[i] - tg[i]);
        }
    }
    __syncthreads();

    // Publish block partials via L2 float atomics (85 distinct addresses).
    if (t < N_BINS) atomicAdd(&g_acc[t], sd[t]);
    __syncthreads();
    if (t == 0) {
        __threadfence();                   // one release fence per block
        unsigned int ticket = atomicAdd(&g_count, 1u);
        islast = (ticket == NBLOCKS - 1u);
    }
    __syncthreads();

    if (islast) {
        __shared__ float d[N_BINS];
        if (t == 0) __threadfence();       // acquire side
        __syncthreads();
        if (t < N_BINS) {
            float v = atomicExch(&g_acc[t], 0.0f);   // read + reset, L2-coherent
            d[t] = fabsf(v);
        }
        __syncthreads();
        if (t == 0) {
            float cum = 0.f, loss = 0.f;
            #pragma unroll
            for (int j = 0; j < N_BINS; j++) {
                cum += d[j];
                loss += cum / (float)(j + 1);
            }
            out[0] = loss * 0.1f;
            atomicExch(&g_count, 0u);
            atomicExch(&g_work,  0u);      // reset queue for next replay
        }
    }
}

extern "C" void kernel_launch(void* const* d_in, const int* in_sizes, int n_in,
                              void* d_out, int out_size)
{
    const float* in = (const float*)d_in[0];
    const float* tg = (const float*)d_in[1];
    int total = in_sizes[0];                     // 500000 * 85
    int nchunk = total / CHUNK_FLOATS;           // 20833
    int tail_start = nchunk * CHUNK_FLOATS;      // 42,499,320 (680-elem tail)

    cudaFuncSetAttribute(emd_fused, cudaFuncAttributeMaxDynamicSharedMemorySize,
                         DYN_SMEM);

    emd_fused<<<NBLOCKS, BLOCK_THREADS, DYN_SMEM>>>(in, tg, nchunk, tail_start,
                                                    total, (float*)d_out);
}

// round 13
// speedup vs baseline: 1.0104x; 1.0104x over previous
#include <cuda_runtime.h>
#include <cstdint>

#define N_BINS 85
#define NBLOCKS 592             // 4 CTAs/SM * 148 SMs (64-reg budget)
#define GROUPS_PER_BLOCK 3
#define ACTIVE_THREADS (GROUPS_PER_BLOCK * N_BINS)   // 255
#define BLOCK_THREADS 256
#define TOTAL_GROUPS (NBLOCKS * GROUPS_PER_BLOCK)    // 1776

// Globals (zero at module load; last block resets via atomicExch each call,
// so graph replays are deterministic). No dynamic allocation.
__device__ float g_acc[N_BINS];
__device__ unsigned int g_count;

// 256-bit global load (Blackwell LDG.E.256). Requires 32B-aligned address:
// cudaMalloc base is 256B-aligned and all offsets are multiples of 32B.
__device__ __forceinline__ void ldg256(const float* __restrict__ p, float r[8]) {
    asm volatile("ld.global.nc.v8.f32 {%0,%1,%2,%3,%4,%5,%6,%7}, [%8];"
                 : "=f"(r[0]), "=f"(r[1]), "=f"(r[2]), "=f"(r[3]),
                   "=f"(r[4]), "=f"(r[5]), "=f"(r[6]), "=f"(r[7])
                 : "l"(p));
}

// ---------------------------------------------------------------------------
// 256-bit-load version. Super-row = 8 rows = 680 floats = 85 float8 slots.
// Thread at position p owns slot p: fixed columns (8p+k) mod 85, k=0..7
// (8*85 ≡ 0 mod 85, so the map is super-row-invariant). Grid-stride over
// 62500 super-rows; one LDG.E.256 per array per iteration (1024B/warp/instr,
// half the request count of the float4 variant).
// Epilogue: one fence per block + ticket; last block finishes (proven cheap).
// ---------------------------------------------------------------------------
__global__ void __launch_bounds__(BLOCK_THREADS, 4)
emd_fused(const float* __restrict__ in, const float* __restrict__ tg,
          int nsuper8, int total_elems, float* __restrict__ out)
{
    __shared__ float sd[N_BINS];
    __shared__ int islast;
    int t = threadIdx.x;
    if (t < N_BINS) sd[t] = 0.0f;

    float acc[8];
    #pragma unroll
    for (int k = 0; k < 8; k++) acc[k] = 0.0f;

    int p = t % N_BINS;
    if (t < ACTIVE_THREADS) {
        int g = blockIdx.x * GROUPS_PER_BLOCK + (t / N_BINS);
        #pragma unroll 2
        for (int s = g; s < nsuper8; s += TOTAL_GROUPS) {
            // float offset of this thread's float8 slot in super-row s
            size_t off = ((size_t)s * N_BINS + p) * 8;
            float a[8], b[8];
            ldg256(in + off, a);
            ldg256(tg + off, b);
            #pragma unroll
            for (int k = 0; k < 8; k++) acc[k] += a[k] - b[k];
        }
    }
    __syncthreads();
    if (t < ACTIVE_THREADS) {
        #pragma unroll
        for (int k = 0; k < 8; k++) {
            atomicAdd(&sd[(8 * p + k) % N_BINS], acc[k]);
        }
    }
    // Tail rows (B % 8 != 0): scalar, block 0 only. (B=500000 -> empty loop.)
    if (blockIdx.x == 0) {
        int tail_start = nsuper8 * (8 * N_BINS);
        for (int i = tail_start + t; i < total_elems; i += BLOCK_THREADS) {
            atomicAdd(&sd[i % N_BINS], in[i] - tg[i]);
        }
    }
    __syncthreads();

    // Publish block partials via L2 float atomics (85 distinct addresses).
    if (t < N_BINS) atomicAdd(&g_acc[t], sd[t]);
    __syncthreads();          // publishers' atomics visible to t0 (block scope)
    if (t == 0) {
        __threadfence();      // ONE cumulative release fence per block
        unsigned int ticket = atomicAdd(&g_count, 1u);
        islast = (ticket == NBLOCKS - 1u);
    }
    __syncthreads();

    if (islast) {
        __shared__ float d[N_BINS];
        if (t == 0) __threadfence();           // acquire side
        __syncthreads();
        if (t < N_BINS) {
            // L2-coherent read + reset in one atomic; no L1 staleness possible.
            float v = atomicExch(&g_acc[t], 0.0f);
            d[t] = fabsf(v);
        }
        __syncthreads();
        if (t == 0) {
            float cum = 0.f, loss = 0.f;
            #pragma unroll
            for (int j = 0; j < N_BINS; j++) {
                cum += d[j];
                loss += cum / (float)(j + 1);
            }
            out[0] = loss * 0.1f;
            atomicExch(&g_count, 0u);          // reset ticket for next replay
        }
    }
}

extern "C" void kernel_launch(void* const* d_in, const int* in_sizes, int n_in,
                              void* d_out, int out_size)
{
    const float* in = (const float*)d_in[0];
    const float* tg = (const float*)d_in[1];
    int total = in_sizes[0];            // 500000 * 85
    int B = total / N_BINS;
    int nsuper8 = B / 8;                // 62500 super-rows of 8 rows

    emd_fused<<<NBLOCKS, BLOCK_THREADS>>>(in, tg, nsuper8, total, (float*)d_out);
}